// round 8
// baseline (speedup 1.0000x reference)
#include <cuda_runtime.h>
#include <math.h>

// Problem constants (fixed by the reference setup_inputs)
#define B    4
#define C    64
#define Kc   19
#define HW   262144          // 512*512
#define EPSF 1e-7f

#define THREADS  256

// ---- stats kernel tiling ----
#define CHUNK_S  8192                   // pixels per stats block
#define SCHUNKS  (HW / CHUNK_S)         // 32
#define CG       8                      // channels per stats block (4 pairs)
#define NCG      (C / CG)               // 8
#define SITERS   (CHUNK_S / (THREADS*4))// 8 float4 per thread per channel
#define STATS_SMEM (Kc * THREADS * 16)  // 77824 B: float4 slab

// ---- apply kernel tiling ----
#define CHUNK_A  1024                   // pixels per apply block
#define ACHUNKS  (HW / CHUNK_A)         // 256
#define CGA      32                     // channels per apply block
#define NCGA     (C / CGA)              // 2

// ---- finalize tiling ----
#define FCQ      4                      // channel-quarters per image
#define FCW      (C / FCQ)              // 16 channels per finalize block

// -------- device scratch (no allocations allowed) --------
__device__ float2 g_acc[B * Kc * C];     // (sum, sumsq) per (b,k,c)
__device__ int    g_cnt[B * Kc];
__device__ float2 g_tab[B * C * Kc];     // (scale, shift) per (b,c,k)

// -------- K0: zero accumulators (graph replays -> must run every launch) ----
__global__ void k_zero() {
    int tid = blockIdx.x * blockDim.x + threadIdx.x;
    int n = B * Kc * C;
    for (int i = tid; i < n; i += gridDim.x * blockDim.x)
        g_acc[i] = make_float2(0.f, 0.f);
    if (tid < B * Kc) g_cnt[tid] = 0;
}

// -------- K1: atomic-free stats, channel-PAIRED float4 slabs + fused counts ----
// block = (b, pixel chunk, channel group of 8 = 4 pairs); grid = 1024
__global__ __launch_bounds__(THREADS) void k_stats(const float* __restrict__ x,
                                                   const int* __restrict__ gt) {
    extern __shared__ float4 s_acc[];                 // [Kc][THREADS] = 77824 B
    __shared__ int s_cnt[Kc];

    const int bid   = blockIdx.x;
    const int cg    = bid % NCG;
    const int chunk = (bid / NCG) % SCHUNKS;
    const int b     = bid / (NCG * SCHUNKS);
    const int tid   = threadIdx.x;
    const int lane  = tid & 31;
    const int wid   = tid >> 5;
    const bool docnt = (cg == 0);

    if (docnt && tid < Kc) s_cnt[tid] = 0;
    if (docnt) __syncthreads();

    // load this thread's 32 labels once, packed 4-per-register (reused all passes)
    unsigned int lbl[SITERS];
    {
        const int4* gt4 = (const int4*)(gt + (size_t)b * HW + (size_t)chunk * CHUNK_S);
        #pragma unroll
        for (int i = 0; i < SITERS; i++) {
            int4 g = gt4[i * THREADS + tid];
            lbl[i] = (unsigned)g.x | ((unsigned)g.y << 8)
                   | ((unsigned)g.z << 16) | ((unsigned)g.w << 24);
            if (docnt) {
                atomicAdd(&s_cnt[g.x], 1); atomicAdd(&s_cnt[g.y], 1);
                atomicAdd(&s_cnt[g.z], 1); atomicAdd(&s_cnt[g.w], 1);
            }
        }
    }
    if (docnt) {
        __syncthreads();
        if (tid < Kc && s_cnt[tid] > 0)
            atomicAdd(&g_cnt[b * Kc + tid], s_cnt[tid]);
    }

    // 4 passes, 2 channels each: slab holds (sum0, sq0, sum1, sq1)
    for (int cp = 0; cp < CG / 2; cp++) {
        const int c0 = cg * CG + cp * 2;
        __syncthreads();
        #pragma unroll
        for (int k = 0; k < Kc; k++)
            s_acc[k * THREADS + tid] = make_float4(0.f, 0.f, 0.f, 0.f);
        __syncthreads();

        const float4* xp0 = (const float4*)(x + ((size_t)(b * C + c0)) * HW
                                              + (size_t)chunk * CHUNK_S);
        const float4* xp1 = (const float4*)(x + ((size_t)(b * C + c0 + 1)) * HW
                                              + (size_t)chunk * CHUNK_S);
        #pragma unroll
        for (int i = 0; i < SITERS; i++) {
            float4 v0 = xp0[i * THREADS + tid];
            float4 v1 = xp1[i * THREADS + tid];
            unsigned int L = lbl[i];
            {
                float4* p = &s_acc[(L & 0xffu) * THREADS + tid];
                float4 a = *p;
                a.x += v0.x; a.y = fmaf(v0.x, v0.x, a.y);
                a.z += v1.x; a.w = fmaf(v1.x, v1.x, a.w);
                *p = a;
            }
            {
                float4* p = &s_acc[((L >> 8) & 0xffu) * THREADS + tid];
                float4 a = *p;
                a.x += v0.y; a.y = fmaf(v0.y, v0.y, a.y);
                a.z += v1.y; a.w = fmaf(v1.y, v1.y, a.w);
                *p = a;
            }
            {
                float4* p = &s_acc[((L >> 16) & 0xffu) * THREADS + tid];
                float4 a = *p;
                a.x += v0.z; a.y = fmaf(v0.z, v0.z, a.y);
                a.z += v1.z; a.w = fmaf(v1.z, v1.z, a.w);
                *p = a;
            }
            {
                float4* p = &s_acc[(L >> 24) * THREADS + tid];
                float4 a = *p;
                a.x += v0.w; a.y = fmaf(v0.w, v0.w, a.y);
                a.z += v1.w; a.w = fmaf(v1.w, v1.w, a.w);
                *p = a;
            }
        }
        __syncthreads();

        // reduce 256 columns -> 1 per class; warp w handles classes w, w+8, w+16
        for (int k = wid; k < Kc; k += 8) {
            float4 s = make_float4(0.f, 0.f, 0.f, 0.f);
            #pragma unroll
            for (int j = 0; j < THREADS / 32; j++) {
                float4 a = s_acc[k * THREADS + lane + 32 * j];
                s.x += a.x; s.y += a.y; s.z += a.z; s.w += a.w;
            }
            #pragma unroll
            for (int d = 16; d > 0; d >>= 1) {
                s.x += __shfl_down_sync(0xffffffffu, s.x, d);
                s.y += __shfl_down_sync(0xffffffffu, s.y, d);
                s.z += __shfl_down_sync(0xffffffffu, s.z, d);
                s.w += __shfl_down_sync(0xffffffffu, s.w, d);
            }
            if (lane == 0) {
                float2* d0 = &g_acc[(b * Kc + k) * C + c0];
                float2* d1 = &g_acc[(b * Kc + k) * C + c0 + 1];
                atomicAdd(&d0->x, s.x);
                atomicAdd(&d0->y, s.y);
                atomicAdd(&d1->x, s.z);
                atomicAdd(&d1->y, s.w);
            }
        }
    }
}

// -------- K2: finalize stats + mixing einsum -> (scale,shift) table ----
// grid = B*FCQ = 16; block owns channels [cq*16, cq*16+16) of image b
__global__ __launch_bounds__(256) void k_finalize(const float* __restrict__ aug) {
    const int b  = blockIdx.x / FCQ;
    const int c0 = (blockIdx.x % FCQ) * FCW;
    const int tid = threadIdx.x;

    __shared__ float s_mean[Kc * FCW];
    __shared__ float s_std [Kc * FCW];
    __shared__ float s_w   [Kc * Kc];
    __shared__ float s_wsum[Kc];
    __shared__ float s_cntf[Kc];

    if (tid < Kc) s_cntf[tid] = (float)g_cnt[b * Kc + tid];
    __syncthreads();

    for (int i = tid; i < Kc * Kc; i += blockDim.x) {
        int k = i % Kc;
        float v = aug[b * Kc * Kc + i];
        s_w[i] = (s_cntf[k] > 0.f) ? v : 0.f;
    }
    for (int i = tid; i < Kc * FCW; i += blockDim.x) {      // i = k*FCW + cl
        int k = i / FCW, cl = i % FCW;
        float cs = (s_cntf[k] > 0.f) ? s_cntf[k] : 1.f;
        float2 a = g_acc[(b * Kc + k) * C + c0 + cl];
        float m = a.x / cs;
        float var = fmaxf(a.y / cs - m * m, 0.f);
        s_mean[i] = m;
        s_std[i]  = sqrtf(var) + EPSF;
    }
    __syncthreads();

    if (tid < Kc) {
        float s = 0.f;
        #pragma unroll
        for (int k = 0; k < Kc; k++) s += s_w[tid * Kc + k];
        s_wsum[tid] = fmaxf(s, EPSF);
    }
    __syncthreads();

    for (int idx = tid; idx < Kc * FCW; idx += blockDim.x) { // idx = i*FCW + cl
        int i = idx / FCW;
        int cl = idx % FCW;
        float inv = 1.f / s_wsum[i];
        float mm = 0.f, ms = 0.f;
        #pragma unroll
        for (int k = 0; k < Kc; k++) {
            float wn = s_w[i * Kc + k] * inv;
            mm += wn * s_mean[k * FCW + cl];
            ms += wn * s_std [k * FCW + cl];
        }
        float sc = ms / s_std[idx];
        g_tab[(b * C + c0 + cl) * Kc + i] = make_float2(sc, mm - s_mean[idx] * sc);
    }
}

// -------- K3: apply out = x * scale[b,c,g] + shift[b,c,g] ----
// block = (b, pixel chunk of 1024, channel half); grid = B*ACHUNKS*NCGA = 2048
__global__ __launch_bounds__(THREADS) void k_apply(const float* __restrict__ x,
                                                   const int* __restrict__ gt,
                                                   float* __restrict__ out) {
    __shared__ float2 s_tab[CGA][Kc + 1];                  // 5.1 KB

    const int bid   = blockIdx.x;
    const int cga   = bid % NCGA;
    const int chunk = (bid / NCGA) % ACHUNKS;
    const int b     = bid / (NCGA * ACHUNKS);
    const int tid   = threadIdx.x;
    const int cbase = cga * CGA;

    for (int i = tid; i < CGA * Kc; i += THREADS) {
        int c = i / Kc, k = i % Kc;
        s_tab[c][k] = g_tab[(b * C + cbase + c) * Kc + k];
    }
    const int4 g = ((const int4*)(gt + (size_t)b * HW + (size_t)chunk * CHUNK_A))[tid];
    __syncthreads();

    #pragma unroll 4
    for (int c = 0; c < CGA; c++) {
        const size_t base = ((size_t)(b * C + cbase + c)) * HW + (size_t)chunk * CHUNK_A;
        float4 v = ((const float4*)(x + base))[tid];
        float2 t0 = s_tab[c][g.x];
        float2 t1 = s_tab[c][g.y];
        float2 t2 = s_tab[c][g.z];
        float2 t3 = s_tab[c][g.w];
        float4 o;
        o.x = fmaf(v.x, t0.x, t0.y);
        o.y = fmaf(v.y, t1.x, t1.y);
        o.z = fmaf(v.z, t2.x, t2.y);
        o.w = fmaf(v.w, t3.x, t3.y);
        ((float4*)(out + base))[tid] = o;
    }
}

extern "C" void kernel_launch(void* const* d_in, const int* in_sizes, int n_in,
                              void* d_out, int out_size) {
    const float* x   = (const float*)d_in[0];
    const int*   gt  = (const int*)d_in[1];
    const float* aug = (const float*)d_in[2];
    float* out = (float*)d_out;

    // host-side attribute set: not an allocation, idempotent, capture-safe
    cudaFuncSetAttribute(k_stats, cudaFuncAttributeMaxDynamicSharedMemorySize,
                         STATS_SMEM);

    k_zero<<<10, 1024>>>();
    k_stats<<<B * SCHUNKS * NCG, THREADS, STATS_SMEM>>>(x, gt);
    k_finalize<<<B * FCQ, 256>>>(aug);
    k_apply<<<B * ACHUNKS * NCGA, THREADS>>>(x, gt, out);
}

// round 9
// speedup vs baseline: 1.0224x; 1.0224x over previous
#include <cuda_runtime.h>
#include <math.h>

// Problem constants (fixed by the reference setup_inputs)
#define B    4
#define C    64
#define Kc   19
#define HW   262144          // 512*512
#define EPSF 1e-7f

#define THREADS  256

// ---- stats kernel tiling ----
#define THREADS_S 128                    // small block -> high CTA residency
#define CHUNK_S  4096                    // pixels per stats block
#define SCHUNKS  (HW / CHUNK_S)          // 64
#define CG       8                       // channels per stats block
#define NCG      (C / CG)                // 8
#define SITERS   (CHUNK_S / (THREADS_S*4)) // 8 float4 per thread per channel

// ---- apply kernel tiling ----
#define CHUNK_A  1024                   // pixels per apply block
#define ACHUNKS  (HW / CHUNK_A)         // 256
#define CGA      32                     // channels per apply block
#define NCGA     (C / CGA)              // 2

// ---- finalize tiling ----
#define FCQ      4                      // channel-quarters per image
#define FCW      (C / FCQ)              // 16 channels per finalize block

// -------- device scratch (no allocations allowed) --------
__device__ float2 g_acc[B * Kc * C];     // (sum, sumsq) per (b,k,c)
__device__ int    g_cnt[B * Kc];
__device__ float2 g_tab[B * C * Kc];     // (scale, shift) per (b,c,k)

// -------- K0: zero accumulators (graph replays -> must run every launch) ----
__global__ void k_zero() {
    int tid = blockIdx.x * blockDim.x + threadIdx.x;
    int n = B * Kc * C;
    for (int i = tid; i < n; i += gridDim.x * blockDim.x)
        g_acc[i] = make_float2(0.f, 0.f);
    if (tid < B * Kc) g_cnt[tid] = 0;
}

// -------- K1: atomic-free stats, small blocks for high residency ----
// block = (b, pixel chunk of 4096, channel group of 8); grid = 2048
__global__ __launch_bounds__(THREADS_S) void k_stats(const float* __restrict__ x,
                                                     const int* __restrict__ gt) {
    __shared__ float2 s_acc[Kc][THREADS_S];               // 19.5 KB
    __shared__ int s_cnt[Kc];

    const int bid   = blockIdx.x;
    const int cg    = bid % NCG;
    const int chunk = (bid / NCG) % SCHUNKS;
    const int b     = bid / (NCG * SCHUNKS);
    const int tid   = threadIdx.x;
    const int lane  = tid & 31;
    const int wid   = tid >> 5;
    const bool docnt = (cg == 0);

    if (docnt && tid < Kc) s_cnt[tid] = 0;
    if (docnt) __syncthreads();

    // load this thread's 32 labels once, packed 4-per-register (reused all passes)
    unsigned int lbl[SITERS];
    {
        const int4* gt4 = (const int4*)(gt + (size_t)b * HW + (size_t)chunk * CHUNK_S);
        #pragma unroll
        for (int i = 0; i < SITERS; i++) {
            int4 g = gt4[i * THREADS_S + tid];
            lbl[i] = (unsigned)g.x | ((unsigned)g.y << 8)
                   | ((unsigned)g.z << 16) | ((unsigned)g.w << 24);
            if (docnt) {
                atomicAdd(&s_cnt[g.x], 1); atomicAdd(&s_cnt[g.y], 1);
                atomicAdd(&s_cnt[g.z], 1); atomicAdd(&s_cnt[g.w], 1);
            }
        }
    }
    if (docnt) {
        __syncthreads();
        if (tid < Kc && s_cnt[tid] > 0)
            atomicAdd(&g_cnt[b * Kc + tid], s_cnt[tid]);
    }

    for (int cc = 0; cc < CG; cc++) {
        const int c = cg * CG + cc;
        __syncthreads();
        #pragma unroll
        for (int k = 0; k < Kc; k++) s_acc[k][tid] = make_float2(0.f, 0.f);
        __syncthreads();

        const float4* xp = (const float4*)(x + ((size_t)(b * C + c)) * HW
                                             + (size_t)chunk * CHUNK_S);
        #pragma unroll
        for (int i = 0; i < SITERS; i++) {
            float4 v = xp[i * THREADS_S + tid];
            unsigned int L = lbl[i];
            float2 a;
            a = s_acc[L & 0xffu][tid];
            a.x += v.x; a.y = fmaf(v.x, v.x, a.y);
            s_acc[L & 0xffu][tid] = a;
            a = s_acc[(L >> 8) & 0xffu][tid];
            a.x += v.y; a.y = fmaf(v.y, v.y, a.y);
            s_acc[(L >> 8) & 0xffu][tid] = a;
            a = s_acc[(L >> 16) & 0xffu][tid];
            a.x += v.z; a.y = fmaf(v.z, v.z, a.y);
            s_acc[(L >> 16) & 0xffu][tid] = a;
            a = s_acc[L >> 24][tid];
            a.x += v.w; a.y = fmaf(v.w, v.w, a.y);
            s_acc[L >> 24][tid] = a;
        }
        __syncthreads();

        // reduce 128 columns -> 1 per class; warp w handles classes w, w+4, ...
        for (int k = wid; k < Kc; k += 4) {
            float2 s = make_float2(0.f, 0.f);
            #pragma unroll
            for (int j = 0; j < THREADS_S / 32; j++) {
                float2 a = s_acc[k][lane + 32 * j];
                s.x += a.x; s.y += a.y;
            }
            #pragma unroll
            for (int d = 16; d > 0; d >>= 1) {
                s.x += __shfl_down_sync(0xffffffffu, s.x, d);
                s.y += __shfl_down_sync(0xffffffffu, s.y, d);
            }
            if (lane == 0) {
                float2* dst = &g_acc[(b * Kc + k) * C + c];
                atomicAdd(&dst->x, s.x);
                atomicAdd(&dst->y, s.y);
            }
        }
    }
}

// -------- K2: finalize stats + mixing einsum -> (scale,shift) table ----
// grid = B*FCQ = 16; block owns channels [cq*16, cq*16+16) of image b
__global__ __launch_bounds__(256) void k_finalize(const float* __restrict__ aug) {
    const int b  = blockIdx.x / FCQ;
    const int c0 = (blockIdx.x % FCQ) * FCW;
    const int tid = threadIdx.x;

    __shared__ float s_mean[Kc * FCW];
    __shared__ float s_std [Kc * FCW];
    __shared__ float s_w   [Kc * Kc];
    __shared__ float s_wsum[Kc];
    __shared__ float s_cntf[Kc];

    if (tid < Kc) s_cntf[tid] = (float)g_cnt[b * Kc + tid];
    __syncthreads();

    for (int i = tid; i < Kc * Kc; i += blockDim.x) {
        int k = i % Kc;
        float v = aug[b * Kc * Kc + i];
        s_w[i] = (s_cntf[k] > 0.f) ? v : 0.f;
    }
    for (int i = tid; i < Kc * FCW; i += blockDim.x) {      // i = k*FCW + cl
        int k = i / FCW, cl = i % FCW;
        float cs = (s_cntf[k] > 0.f) ? s_cntf[k] : 1.f;
        float2 a = g_acc[(b * Kc + k) * C + c0 + cl];
        float m = a.x / cs;
        float var = fmaxf(a.y / cs - m * m, 0.f);
        s_mean[i] = m;
        s_std[i]  = sqrtf(var) + EPSF;
    }
    __syncthreads();

    if (tid < Kc) {
        float s = 0.f;
        #pragma unroll
        for (int k = 0; k < Kc; k++) s += s_w[tid * Kc + k];
        s_wsum[tid] = fmaxf(s, EPSF);
    }
    __syncthreads();

    for (int idx = tid; idx < Kc * FCW; idx += blockDim.x) { // idx = i*FCW + cl
        int i = idx / FCW;
        int cl = idx % FCW;
        float inv = 1.f / s_wsum[i];
        float mm = 0.f, ms = 0.f;
        #pragma unroll
        for (int k = 0; k < Kc; k++) {
            float wn = s_w[i * Kc + k] * inv;
            mm += wn * s_mean[k * FCW + cl];
            ms += wn * s_std [k * FCW + cl];
        }
        float sc = ms / s_std[idx];
        g_tab[(b * C + c0 + cl) * Kc + i] = make_float2(sc, mm - s_mean[idx] * sc);
    }
}

// -------- K3: apply out = x * scale[b,c,g] + shift[b,c,g] ----
// block = (b, pixel chunk of 1024, channel half); grid = B*ACHUNKS*NCGA = 2048
__global__ __launch_bounds__(THREADS) void k_apply(const float* __restrict__ x,
                                                   const int* __restrict__ gt,
                                                   float* __restrict__ out) {
    __shared__ float2 s_tab[CGA][Kc + 1];                  // 5.1 KB

    const int bid   = blockIdx.x;
    const int cga   = bid % NCGA;
    const int chunk = (bid / NCGA) % ACHUNKS;
    const int b     = bid / (NCGA * ACHUNKS);
    const int tid   = threadIdx.x;
    const int cbase = cga * CGA;

    for (int i = tid; i < CGA * Kc; i += THREADS) {
        int c = i / Kc, k = i % Kc;
        s_tab[c][k] = g_tab[(b * C + cbase + c) * Kc + k];
    }
    const int4 g = ((const int4*)(gt + (size_t)b * HW + (size_t)chunk * CHUNK_A))[tid];
    __syncthreads();

    #pragma unroll 4
    for (int c = 0; c < CGA; c++) {
        const size_t base = ((size_t)(b * C + cbase + c)) * HW + (size_t)chunk * CHUNK_A;
        float4 v = ((const float4*)(x + base))[tid];
        float2 t0 = s_tab[c][g.x];
        float2 t1 = s_tab[c][g.y];
        float2 t2 = s_tab[c][g.z];
        float2 t3 = s_tab[c][g.w];
        float4 o;
        o.x = fmaf(v.x, t0.x, t0.y);
        o.y = fmaf(v.y, t1.x, t1.y);
        o.z = fmaf(v.z, t2.x, t2.y);
        o.w = fmaf(v.w, t3.x, t3.y);
        ((float4*)(out + base))[tid] = o;
    }
}

extern "C" void kernel_launch(void* const* d_in, const int* in_sizes, int n_in,
                              void* d_out, int out_size) {
    const float* x   = (const float*)d_in[0];
    const int*   gt  = (const int*)d_in[1];
    const float* aug = (const float*)d_in[2];
    float* out = (float*)d_out;

    k_zero<<<10, 1024>>>();
    k_stats<<<B * SCHUNKS * NCG, THREADS_S>>>(x, gt);
    k_finalize<<<B * FCQ, 256>>>(aug);
    k_apply<<<B * ACHUNKS * NCGA, THREADS>>>(x, gt, out);
}

// round 10
// speedup vs baseline: 1.0463x; 1.0233x over previous
#include <cuda_runtime.h>
#include <math.h>

// Problem constants (fixed by the reference setup_inputs)
#define B    4
#define C    64
#define Kc   19
#define HW   262144          // 512*512
#define EPSF 1e-7f

#define THREADS  256

// ---- stats kernel tiling ----
#define THREADS_S 128                      // small block -> high CTA residency
#define CHUNK_S  4096                      // pixels per stats block
#define SCHUNKS  (HW / CHUNK_S)            // 64
#define CG       8                         // channels per stats block (4 pairs)
#define NCG      (C / CG)                  // 8
#define SITERS   (CHUNK_S / (THREADS_S*4)) // 8 float4 per thread per channel

// ---- apply kernel tiling ----
#define CHUNK_A  1024                   // pixels per apply block
#define ACHUNKS  (HW / CHUNK_A)         // 256
#define CGA      32                     // channels per apply block
#define NCGA     (C / CGA)              // 2

// ---- finalize tiling ----
#define FCQ      4                      // channel-quarters per image
#define FCW      (C / FCQ)              // 16 channels per finalize block

// -------- device scratch (no allocations allowed) --------
__device__ float2 g_acc[B * Kc * C];     // (sum, sumsq) per (b,k,c)
__device__ int    g_cnt[B * Kc];
__device__ float2 g_tab[B * C * Kc];     // (scale, shift) per (b,c,k)

// -------- K0: zero accumulators (graph replays -> must run every launch) ----
__global__ void k_zero() {
    int tid = blockIdx.x * blockDim.x + threadIdx.x;
    int n = B * Kc * C;
    for (int i = tid; i < n; i += gridDim.x * blockDim.x)
        g_acc[i] = make_float2(0.f, 0.f);
    if (tid < B * Kc) g_cnt[tid] = 0;
}

// -------- K1: stats: paired-channel float4 slabs + small blocks ----
// slab entry = (sum_c0, sq_c0, sum_c1, sq_c1): 1 LDS.128 + 1 STS.128 per 2 elems
// block = (b, pixel chunk of 4096, channel group of 8 = 4 pairs); grid = 2048
__global__ __launch_bounds__(THREADS_S) void k_stats(const float* __restrict__ x,
                                                     const int* __restrict__ gt) {
    __shared__ float4 s_acc[Kc][THREADS_S];               // 38.9 KB
    __shared__ int s_cnt[Kc];

    const int bid   = blockIdx.x;
    const int cg    = bid % NCG;
    const int chunk = (bid / NCG) % SCHUNKS;
    const int b     = bid / (NCG * SCHUNKS);
    const int tid   = threadIdx.x;
    const int lane  = tid & 31;
    const int wid   = tid >> 5;
    const bool docnt = (cg == 0);

    if (docnt && tid < Kc) s_cnt[tid] = 0;
    if (docnt) __syncthreads();

    // load this thread's 32 labels once, packed 4-per-register (reused all passes)
    unsigned int lbl[SITERS];
    {
        const int4* gt4 = (const int4*)(gt + (size_t)b * HW + (size_t)chunk * CHUNK_S);
        #pragma unroll
        for (int i = 0; i < SITERS; i++) {
            int4 g = gt4[i * THREADS_S + tid];
            lbl[i] = (unsigned)g.x | ((unsigned)g.y << 8)
                   | ((unsigned)g.z << 16) | ((unsigned)g.w << 24);
            if (docnt) {
                atomicAdd(&s_cnt[g.x], 1); atomicAdd(&s_cnt[g.y], 1);
                atomicAdd(&s_cnt[g.z], 1); atomicAdd(&s_cnt[g.w], 1);
            }
        }
    }
    if (docnt) {
        __syncthreads();
        if (tid < Kc && s_cnt[tid] > 0)
            atomicAdd(&g_cnt[b * Kc + tid], s_cnt[tid]);
    }

    // 4 passes, 2 channels each
    #pragma unroll
    for (int cp = 0; cp < CG / 2; cp++) {
        const int c0 = cg * CG + cp * 2;
        __syncthreads();
        #pragma unroll
        for (int k = 0; k < Kc; k++)
            s_acc[k][tid] = make_float4(0.f, 0.f, 0.f, 0.f);
        __syncthreads();

        const float4* xp0 = (const float4*)(x + ((size_t)(b * C + c0)) * HW
                                              + (size_t)chunk * CHUNK_S);
        const float4* xp1 = (const float4*)(x + ((size_t)(b * C + c0 + 1)) * HW
                                              + (size_t)chunk * CHUNK_S);
        #pragma unroll
        for (int i = 0; i < SITERS; i++) {
            float4 v0 = xp0[i * THREADS_S + tid];
            float4 v1 = xp1[i * THREADS_S + tid];
            unsigned int L = lbl[i];
            {
                float4* p = &s_acc[L & 0xffu][tid];
                float4 a = *p;
                a.x += v0.x; a.y = fmaf(v0.x, v0.x, a.y);
                a.z += v1.x; a.w = fmaf(v1.x, v1.x, a.w);
                *p = a;
            }
            {
                float4* p = &s_acc[(L >> 8) & 0xffu][tid];
                float4 a = *p;
                a.x += v0.y; a.y = fmaf(v0.y, v0.y, a.y);
                a.z += v1.y; a.w = fmaf(v1.y, v1.y, a.w);
                *p = a;
            }
            {
                float4* p = &s_acc[(L >> 16) & 0xffu][tid];
                float4 a = *p;
                a.x += v0.z; a.y = fmaf(v0.z, v0.z, a.y);
                a.z += v1.z; a.w = fmaf(v1.z, v1.z, a.w);
                *p = a;
            }
            {
                float4* p = &s_acc[L >> 24][tid];
                float4 a = *p;
                a.x += v0.w; a.y = fmaf(v0.w, v0.w, a.y);
                a.z += v1.w; a.w = fmaf(v1.w, v1.w, a.w);
                *p = a;
            }
        }
        __syncthreads();

        // reduce 128 columns -> 1 per class; warp w handles classes w, w+4, ...
        for (int k = wid; k < Kc; k += 4) {
            float4 s = make_float4(0.f, 0.f, 0.f, 0.f);
            #pragma unroll
            for (int j = 0; j < THREADS_S / 32; j++) {
                float4 a = s_acc[k][lane + 32 * j];
                s.x += a.x; s.y += a.y; s.z += a.z; s.w += a.w;
            }
            #pragma unroll
            for (int d = 16; d > 0; d >>= 1) {
                s.x += __shfl_down_sync(0xffffffffu, s.x, d);
                s.y += __shfl_down_sync(0xffffffffu, s.y, d);
                s.z += __shfl_down_sync(0xffffffffu, s.z, d);
                s.w += __shfl_down_sync(0xffffffffu, s.w, d);
            }
            if (lane == 0) {
                float2* d0 = &g_acc[(b * Kc + k) * C + c0];
                float2* d1 = &g_acc[(b * Kc + k) * C + c0 + 1];
                atomicAdd(&d0->x, s.x);
                atomicAdd(&d0->y, s.y);
                atomicAdd(&d1->x, s.z);
                atomicAdd(&d1->y, s.w);
            }
        }
    }
}

// -------- K2: finalize stats + mixing einsum -> (scale,shift) table ----
// grid = B*FCQ = 16; block owns channels [cq*16, cq*16+16) of image b
__global__ __launch_bounds__(256) void k_finalize(const float* __restrict__ aug) {
    const int b  = blockIdx.x / FCQ;
    const int c0 = (blockIdx.x % FCQ) * FCW;
    const int tid = threadIdx.x;

    __shared__ float s_mean[Kc * FCW];
    __shared__ float s_std [Kc * FCW];
    __shared__ float s_w   [Kc * Kc];
    __shared__ float s_wsum[Kc];
    __shared__ float s_cntf[Kc];

    if (tid < Kc) s_cntf[tid] = (float)g_cnt[b * Kc + tid];
    __syncthreads();

    for (int i = tid; i < Kc * Kc; i += blockDim.x) {
        int k = i % Kc;
        float v = aug[b * Kc * Kc + i];
        s_w[i] = (s_cntf[k] > 0.f) ? v : 0.f;
    }
    for (int i = tid; i < Kc * FCW; i += blockDim.x) {      // i = k*FCW + cl
        int k = i / FCW, cl = i % FCW;
        float cs = (s_cntf[k] > 0.f) ? s_cntf[k] : 1.f;
        float2 a = g_acc[(b * Kc + k) * C + c0 + cl];
        float m = a.x / cs;
        float var = fmaxf(a.y / cs - m * m, 0.f);
        s_mean[i] = m;
        s_std[i]  = sqrtf(var) + EPSF;
    }
    __syncthreads();

    if (tid < Kc) {
        float s = 0.f;
        #pragma unroll
        for (int k = 0; k < Kc; k++) s += s_w[tid * Kc + k];
        s_wsum[tid] = fmaxf(s, EPSF);
    }
    __syncthreads();

    for (int idx = tid; idx < Kc * FCW; idx += blockDim.x) { // idx = i*FCW + cl
        int i = idx / FCW;
        int cl = idx % FCW;
        float inv = 1.f / s_wsum[i];
        float mm = 0.f, ms = 0.f;
        #pragma unroll
        for (int k = 0; k < Kc; k++) {
            float wn = s_w[i * Kc + k] * inv;
            mm += wn * s_mean[k * FCW + cl];
            ms += wn * s_std [k * FCW + cl];
        }
        float sc = ms / s_std[idx];
        g_tab[(b * C + c0 + cl) * Kc + i] = make_float2(sc, mm - s_mean[idx] * sc);
    }
}

// -------- K3: apply out = x * scale[b,c,g] + shift[b,c,g] ----
// block = (b, pixel chunk of 1024, channel half); grid = B*ACHUNKS*NCGA = 2048
__global__ __launch_bounds__(THREADS) void k_apply(const float* __restrict__ x,
                                                   const int* __restrict__ gt,
                                                   float* __restrict__ out) {
    __shared__ float2 s_tab[CGA][Kc + 1];                  // 5.1 KB

    const int bid   = blockIdx.x;
    const int cga   = bid % NCGA;
    const int chunk = (bid / NCGA) % ACHUNKS;
    const int b     = bid / (NCGA * ACHUNKS);
    const int tid   = threadIdx.x;
    const int cbase = cga * CGA;

    for (int i = tid; i < CGA * Kc; i += THREADS) {
        int c = i / Kc, k = i % Kc;
        s_tab[c][k] = g_tab[(b * C + cbase + c) * Kc + k];
    }
    const int4 g = ((const int4*)(gt + (size_t)b * HW + (size_t)chunk * CHUNK_A))[tid];
    __syncthreads();

    #pragma unroll 4
    for (int c = 0; c < CGA; c++) {
        const size_t base = ((size_t)(b * C + cbase + c)) * HW + (size_t)chunk * CHUNK_A;
        float4 v = ((const float4*)(x + base))[tid];
        float2 t0 = s_tab[c][g.x];
        float2 t1 = s_tab[c][g.y];
        float2 t2 = s_tab[c][g.z];
        float2 t3 = s_tab[c][g.w];
        float4 o;
        o.x = fmaf(v.x, t0.x, t0.y);
        o.y = fmaf(v.y, t1.x, t1.y);
        o.z = fmaf(v.z, t2.x, t2.y);
        o.w = fmaf(v.w, t3.x, t3.y);
        ((float4*)(out + base))[tid] = o;
    }
}

extern "C" void kernel_launch(void* const* d_in, const int* in_sizes, int n_in,
                              void* d_out, int out_size) {
    const float* x   = (const float*)d_in[0];
    const int*   gt  = (const int*)d_in[1];
    const float* aug = (const float*)d_in[2];
    float* out = (float*)d_out;

    k_zero<<<10, 1024>>>();
    k_stats<<<B * SCHUNKS * NCG, THREADS_S>>>(x, gt);
    k_finalize<<<B * FCQ, 256>>>(aug);
    k_apply<<<B * ACHUNKS * NCGA, THREADS>>>(x, gt, out);
}